// round 1
// baseline (speedup 1.0000x reference)
#include <cuda_runtime.h>

#define NB   32
#define DD   256
#define MMs  784
#define CINc 2048
#define MAT  (DD*DD)          // 65536
#define BMAT (NB*MAT)         // 2,097,152

// Scratch (device globals; no allocation anywhere)
__device__ float g_y[NB*DD*MMs];      // BN'd ReLU'd activations  [b][d][m]
__device__ float g_mats[11u*BMAT];    // 11 batched 256x256 matrix buffers
__device__ float g_small[16384];      // bn_mean[256], bn_rstd[256], rowmean[8192], tr[32]

// ---------------------------------------------------------------------------
// Reductions
// ---------------------------------------------------------------------------
__device__ __forceinline__ float warpReduce(float v) {
    #pragma unroll
    for (int o = 16; o; o >>= 1) v += __shfl_down_sync(0xffffffffu, v, o);
    return v;
}

// ---------------------------------------------------------------------------
// conv 1x1 GEMM: y[b][d][m] = sum_c w[d][c] * x[b][c][m]
// A = w [256 x 2048] (shared over batch), B = x[b] [2048 x 784]
// ---------------------------------------------------------------------------
__global__ void conv_gemm(const float* __restrict__ x, const float* __restrict__ w,
                          float* __restrict__ y)
{
    const int b  = blockIdx.z;
    const int m0 = blockIdx.y * 64;               // d tile
    const int n0 = blockIdx.x * 64;               // spatial tile
    const float* Bm = x + (size_t)b * CINc * MMs;
    float* Dm = y + (size_t)b * DD * MMs;

    __shared__ float As[16][64];
    __shared__ float Bs[16][64];
    const int tid  = threadIdx.x;
    const int arow = tid >> 2, acq = (tid & 3) << 2;
    const int brow = tid >> 4, bcq = (tid & 15) << 2;
    const int rq   = (tid >> 4) << 2, cq = (tid & 15) << 2;

    float acc[4][4] = {};
    for (int k0 = 0; k0 < CINc; k0 += 16) {
        float4 a4 = *(const float4*)(w + (size_t)(m0 + arow) * CINc + k0 + acq);
        As[acq+0][arow] = a4.x; As[acq+1][arow] = a4.y;
        As[acq+2][arow] = a4.z; As[acq+3][arow] = a4.w;
        const int bc = n0 + bcq;
        float4 b4 = make_float4(0.f, 0.f, 0.f, 0.f);
        if (bc < MMs) b4 = *(const float4*)(Bm + (size_t)(k0 + brow) * MMs + bc);
        *(float4*)(&Bs[brow][bcq]) = b4;
        __syncthreads();
        #pragma unroll
        for (int kk = 0; kk < 16; kk++) {
            float4 av = *(const float4*)(&As[kk][rq]);
            float4 bv = *(const float4*)(&Bs[kk][cq]);
            float ar[4] = {av.x, av.y, av.z, av.w};
            float br[4] = {bv.x, bv.y, bv.z, bv.w};
            #pragma unroll
            for (int i = 0; i < 4; i++)
                #pragma unroll
                for (int j = 0; j < 4; j++)
                    acc[i][j] = fmaf(ar[i], br[j], acc[i][j]);
        }
        __syncthreads();
    }
    #pragma unroll
    for (int i = 0; i < 4; i++) {
        const int r = m0 + rq + i;
        #pragma unroll
        for (int j = 0; j < 4; j++) {
            const int c = n0 + cq + j;
            if (c < MMs) Dm[(size_t)r * MMs + c] = acc[i][j];
        }
    }
}

// ---------------------------------------------------------------------------
// BN stats over (b, m) per channel d
// ---------------------------------------------------------------------------
__global__ void bn_stats(const float* __restrict__ y, float* __restrict__ mean,
                         float* __restrict__ rstd)
{
    const int d = blockIdx.x;
    const int t = threadIdx.x;
    float s = 0.f, s2 = 0.f;
    for (int b = 0; b < NB; b++) {
        const float* p = y + (size_t)b * DD * MMs + (size_t)d * MMs;
        for (int m = t; m < MMs; m += 256) { float v = p[m]; s += v; s2 = fmaf(v, v, s2); }
    }
    __shared__ float sh1[8], sh2[8];
    const int lane = t & 31, wid = t >> 5;
    s = warpReduce(s); s2 = warpReduce(s2);
    if (lane == 0) { sh1[wid] = s; sh2[wid] = s2; }
    __syncthreads();
    if (wid == 0) {
        s  = (lane < 8) ? sh1[lane] : 0.f;
        s2 = (lane < 8) ? sh2[lane] : 0.f;
        s = warpReduce(s); s2 = warpReduce(s2);
        if (lane == 0) {
            const float N = (float)(NB * MMs);
            float mu  = s / N;
            float var = s2 / N - mu * mu;
            mean[d] = mu;
            rstd[d] = rsqrtf(var + 1e-5f);
        }
    }
}

// ---------------------------------------------------------------------------
// BN apply + ReLU (in place) + per-(b,d) row mean for covariance centering
// ---------------------------------------------------------------------------
__global__ void bn_apply(float* __restrict__ y, const float* __restrict__ mean,
                         const float* __restrict__ rstd, const float* __restrict__ gamma,
                         const float* __restrict__ beta, float* __restrict__ rowmean)
{
    const int bd = blockIdx.x;
    const int d  = bd & (DD - 1);
    float* p = y + (size_t)bd * MMs;
    const float mu = mean[d], rs = rstd[d], g = gamma[d], be = beta[d];
    const int t = threadIdx.x;
    float s = 0.f;
    for (int m = t; m < MMs; m += 256) {
        float v = fmaf((p[m] - mu) * rs, g, be);
        v = fmaxf(v, 0.f);
        p[m] = v;
        s += v;
    }
    __shared__ float sh[8];
    const int lane = t & 31, wid = t >> 5;
    s = warpReduce(s);
    if (lane == 0) sh[wid] = s;
    __syncthreads();
    if (wid == 0) {
        s = (lane < 8) ? sh[lane] : 0.f;
        s = warpReduce(s);
        if (lane == 0) rowmean[bd] = s * (1.0f / MMs);
    }
}

// ---------------------------------------------------------------------------
// Covariance: C[b] = (Y Y^T)/784 - mu mu^T   (exactly symmetric by construction)
// ---------------------------------------------------------------------------
__global__ void cov_gemm(const float* __restrict__ y, const float* __restrict__ rowmean,
                         float* __restrict__ C)
{
    const int b  = blockIdx.z;
    const int i0 = blockIdx.y * 64;
    const int j0 = blockIdx.x * 64;
    const float* Yb = y + (size_t)b * DD * MMs;

    __shared__ float Is[16][64];
    __shared__ float Js[16][64];
    const int tid  = threadIdx.x;
    const int lrow = tid >> 2, lkq = (tid & 3) << 2;
    const int rq   = (tid >> 4) << 2, cq = (tid & 15) << 2;

    float acc[4][4] = {};
    for (int k0 = 0; k0 < MMs; k0 += 16) {   // 784 = 49*16
        float4 a4 = *(const float4*)(Yb + (size_t)(i0 + lrow) * MMs + k0 + lkq);
        float4 b4 = *(const float4*)(Yb + (size_t)(j0 + lrow) * MMs + k0 + lkq);
        Is[lkq+0][lrow] = a4.x; Is[lkq+1][lrow] = a4.y;
        Is[lkq+2][lrow] = a4.z; Is[lkq+3][lrow] = a4.w;
        Js[lkq+0][lrow] = b4.x; Js[lkq+1][lrow] = b4.y;
        Js[lkq+2][lrow] = b4.z; Js[lkq+3][lrow] = b4.w;
        __syncthreads();
        #pragma unroll
        for (int kk = 0; kk < 16; kk++) {
            float4 av = *(const float4*)(&Is[kk][rq]);
            float4 bv = *(const float4*)(&Js[kk][cq]);
            float ar[4] = {av.x, av.y, av.z, av.w};
            float br[4] = {bv.x, bv.y, bv.z, bv.w};
            #pragma unroll
            for (int i = 0; i < 4; i++)
                #pragma unroll
                for (int j = 0; j < 4; j++)
                    acc[i][j] = fmaf(ar[i], br[j], acc[i][j]);
        }
        __syncthreads();
    }
    const float invM = 1.0f / (float)MMs;
    const float* mu = rowmean + b * DD;
    float* Cb = C + (size_t)b * MAT;
    #pragma unroll
    for (int i = 0; i < 4; i++) {
        const int r = i0 + rq + i;
        const float mi = mu[r];
        #pragma unroll
        for (int j = 0; j < 4; j++) {
            const int c = j0 + cq + j;
            Cb[r * DD + c] = acc[i][j] * invM - mi * mu[c];
        }
    }
}

// ---------------------------------------------------------------------------
// trace of batched 256x256
// ---------------------------------------------------------------------------
__global__ void tracek(const float* __restrict__ X, float* __restrict__ tr)
{
    const int b = blockIdx.x;
    const int t = threadIdx.x;
    float v = X[(size_t)b * MAT + t * 257];
    __shared__ float sh[8];
    const int lane = t & 31, wid = t >> 5;
    v = warpReduce(v);
    if (lane == 0) sh[wid] = v;
    __syncthreads();
    if (wid == 0) {
        v = (lane < 8) ? sh[lane] : 0.f;
        v = warpReduce(v);
        if (lane == 0) tr[b] = v;
    }
}

// C /= tr[b] (in place); M = C_normalized + diag(1e-10 + 1e-9*jitter)
__global__ void scale_and_diag(float* __restrict__ C, const float* __restrict__ tr,
                               const float* __restrict__ jitter, float* __restrict__ Mo)
{
    const int idx = blockIdx.x * 256 + threadIdx.x;
    const int b = idx >> 16, rc = idx & 65535, r = rc >> 8, c = rc & 255;
    float v = C[idx] * (1.0f / tr[b]);
    C[idx] = v;
    if (r == c) v += 1e-10f + 1e-9f * jitter[r];
    Mo[idx] = v;
}

// M = L + diag(Ij)
__global__ void add_diag(const float* __restrict__ L, const float* __restrict__ jitter,
                         float* __restrict__ Mo)
{
    const int idx = blockIdx.x * 256 + threadIdx.x;
    const int rc = idx & 65535, r = rc >> 8, c = rc & 255;
    float v = L[idx];
    if (r == c) v += 1e-10f + 1e-9f * jitter[r];
    Mo[idx] = v;
}

// A = M/tr[b];  ZY0 = 0.5*(3I - A)
__global__ void prep_ns(const float* __restrict__ Mi, const float* __restrict__ tr,
                        float* __restrict__ A, float* __restrict__ ZY)
{
    const int idx = blockIdx.x * 256 + threadIdx.x;
    const int b = idx >> 16, rc = idx & 65535, r = rc >> 8, c = rc & 255;
    float a = Mi[idx] * (1.0f / tr[b]);
    A[idx] = a;
    ZY[idx] = (r == c ? 1.5f : 0.0f) - 0.5f * a;
}

// ---------------------------------------------------------------------------
// Batched 256x256x256 GEMM, row-major, batch=32.
// epi 0: D = P;  epi 1: D = 0.5*(3I - P);  epi 2: D = P * rsqrt(tr[b])
// ---------------------------------------------------------------------------
__global__ void bgemm256(const float* __restrict__ Ab, const float* __restrict__ Bb,
                         float* __restrict__ Db, const float* __restrict__ tr, int epi)
{
    const int b = blockIdx.z;
    const float* A  = Ab + (size_t)b * MAT;
    const float* Bm = Bb + (size_t)b * MAT;
    float* Dm = Db + (size_t)b * MAT;
    const int m0 = blockIdx.y * 64, n0 = blockIdx.x * 64;

    __shared__ float As[16][64];
    __shared__ float Bs[16][64];
    const int tid  = threadIdx.x;
    const int arow = tid >> 2, acq = (tid & 3) << 2;
    const int brow = tid >> 4, bcq = (tid & 15) << 2;
    const int rq   = (tid >> 4) << 2, cq = (tid & 15) << 2;

    float acc[4][4] = {};
    for (int k0 = 0; k0 < 256; k0 += 16) {
        float4 a4 = *(const float4*)(A  + (m0 + arow) * 256 + k0 + acq);
        float4 b4 = *(const float4*)(Bm + (k0 + brow) * 256 + n0 + bcq);
        As[acq+0][arow] = a4.x; As[acq+1][arow] = a4.y;
        As[acq+2][arow] = a4.z; As[acq+3][arow] = a4.w;
        *(float4*)(&Bs[brow][bcq]) = b4;
        __syncthreads();
        #pragma unroll
        for (int kk = 0; kk < 16; kk++) {
            float4 av = *(const float4*)(&As[kk][rq]);
            float4 bv = *(const float4*)(&Bs[kk][cq]);
            float ar[4] = {av.x, av.y, av.z, av.w};
            float br[4] = {bv.x, bv.y, bv.z, bv.w};
            #pragma unroll
            for (int i = 0; i < 4; i++)
                #pragma unroll
                for (int j = 0; j < 4; j++)
                    acc[i][j] = fmaf(ar[i], br[j], acc[i][j]);
        }
        __syncthreads();
    }
    const float s = (epi == 2) ? rsqrtf(tr[b]) : 1.0f;
    #pragma unroll
    for (int i = 0; i < 4; i++) {
        const int r = m0 + rq + i;
        #pragma unroll
        for (int j = 0; j < 4; j++) {
            const int c = n0 + cq + j;
            float v = acc[i][j];
            if (epi == 1)      v = (r == c ? 1.5f : 0.0f) - 0.5f * v;
            else if (epi == 2) v *= s;
            Dm[r * 256 + c] = v;
        }
    }
}

// ---------------------------------------------------------------------------
// SICE proximal step + symmetrization, in place on L (pair-owned elements)
// ---------------------------------------------------------------------------
__device__ __forceinline__ float sice_f(float L, float g12, float dec)
{
    float lp = fmaxf(L, 0.f);
    float lm = fmaxf(-L, 0.f);
    lp = fmaxf(lp - dec * (g12 + 0.07f), 0.f);
    lm = fmaxf(lm - dec * (-g12 + 0.07f), 0.f);
    return lp - lm;
}

__global__ void sice_update(float* __restrict__ L, const float* __restrict__ G,
                            const float* __restrict__ Cn, float dec)
{
    const int b = blockIdx.y, i = blockIdx.x, j = threadIdx.x;
    if (j < i) return;
    const size_t base = (size_t)b * MAT;
    const size_t ij = base + i * 256 + j;
    const size_t ji = base + j * 256 + i;
    const float f1 = sice_f(L[ij], Cn[ij] - G[ij], dec);
    const float f2 = sice_f(L[ji], Cn[ji] - G[ji], dec);
    const float v = 0.5f * (f1 + f2);
    L[ij] = v; L[ji] = v;
}

// ---------------------------------------------------------------------------
// Triuvec output: out[b][k] = L[b][i][j] * rsqrt(tr[b]),  k over j>=i row-major
// ---------------------------------------------------------------------------
__global__ void gather_out(const float* __restrict__ L, const float* __restrict__ tr,
                           float* __restrict__ out)
{
    const int b = blockIdx.y, i = blockIdx.x, j = threadIdx.x;
    if (j < i) return;
    const float s = rsqrtf(tr[b]);
    const int k = i * 256 - (i * (i - 1)) / 2 + (j - i);
    out[(size_t)b * 32896 + k] = L[(size_t)b * MAT + i * 256 + j] * s;
}

// ---------------------------------------------------------------------------
// Host orchestration
// ---------------------------------------------------------------------------
static void run_inv_sqrtm(const float* Min, float* zz, float* tr,
                          float* A, float* Y, float* Z, float* Y2, float* Z2, float* ZYt)
{
    const dim3 gg(4, 4, NB);
    tracek<<<NB, 256>>>(Min, tr);
    prep_ns<<<BMAT / 256, 256>>>(Min, tr, A, Z);          // Z holds ZY0
    bgemm256<<<gg, 256>>>(A, Z, Y, tr, 0);                // Y = A @ ZY0
    float *Yc = Y, *Zc = Z, *Ya = Y2, *Za = Z2;
    for (int it = 0; it < 5; it++) {                      // NS_ITERS - 2
        bgemm256<<<gg, 256>>>(Zc, Yc, ZYt, tr, 1);        // ZY = 0.5(3I - Z@Y)
        bgemm256<<<gg, 256>>>(Yc, ZYt, Ya, tr, 0);        // Y' = Y @ ZY
        bgemm256<<<gg, 256>>>(ZYt, Zc, Za, tr, 0);        // Z' = ZY @ Z
        float* t1 = Yc; Yc = Ya; Ya = t1;
        float* t2 = Zc; Zc = Za; Za = t2;
    }
    bgemm256<<<gg, 256>>>(Zc, Yc, ZYt, tr, 1);            // 0.5(3I - Z@Y)
    bgemm256<<<gg, 256>>>(ZYt, Zc, zz, tr, 2);            // @ Z * tr^-0.5
}

extern "C" void kernel_launch(void* const* d_in, const int* in_sizes, int n_in,
                              void* d_out, int out_size)
{
    (void)in_sizes; (void)n_in; (void)out_size;
    const float* x      = (const float*)d_in[0];
    const float* w      = (const float*)d_in[1];
    const float* gamma  = (const float*)d_in[2];
    const float* beta   = (const float*)d_in[3];
    const float* jitter = (const float*)d_in[4];
    float* out = (float*)d_out;

    float *y, *mats, *small;
    cudaGetSymbolAddress((void**)&y, g_y);
    cudaGetSymbolAddress((void**)&mats, g_mats);
    cudaGetSymbolAddress((void**)&small, g_small);

    float* Cn  = mats + 0u * BMAT;
    float* Mb  = mats + 1u * BMAT;
    float* A   = mats + 2u * BMAT;
    float* Y   = mats + 3u * BMAT;
    float* Z   = mats + 4u * BMAT;
    float* Y2  = mats + 5u * BMAT;
    float* Z2  = mats + 6u * BMAT;
    float* ZYt = mats + 7u * BMAT;
    float* zz  = mats + 8u * BMAT;
    float* G   = mats + 9u * BMAT;
    float* LLT = mats + 10u * BMAT;

    float* bn_mean = small;
    float* bn_rstd = small + 256;
    float* rowmean = small + 512;
    float* tr      = small + 512 + NB * DD;

    const dim3 gg(4, 4, NB);

    // Stage 1: conv + BN + ReLU
    conv_gemm<<<dim3(13, 4, NB), 256>>>(x, w, y);
    bn_stats<<<DD, 256>>>(y, bn_mean, bn_rstd);
    bn_apply<<<NB * DD, 256>>>(y, bn_mean, bn_rstd, gamma, beta, rowmean);

    // Stage 2: covariance, trace-normalize, jitter diag
    cov_gemm<<<dim3(4, 4, NB), 256>>>(y, rowmean, Cn);
    tracek<<<NB, 256>>>(Cn, tr);
    scale_and_diag<<<BMAT / 256, 256>>>(Cn, tr, jitter, Mb);  // Cn normalized == sym_C

    // Stage 3: LLT init = inv_sqrtm(C + Ij)^2
    run_inv_sqrtm(Mb, zz, tr, A, Y, Z, Y2, Z2, ZYt);
    bgemm256<<<gg, 256>>>(zz, zz, LLT, tr, 0);

    // Stage 4: SICE loop. i=2 has dec==0 -> exact identity, skipped.
    for (int i = 0; i < 2; i++) {
        add_diag<<<BMAT / 256, 256>>>(LLT, jitter, Mb);
        run_inv_sqrtm(Mb, zz, tr, A, Y, Z, Y2, Z2, ZYt);
        bgemm256<<<gg, 256>>>(zz, zz, G, tr, 0);
        const float dec = 5.0f * (1.0f - (float)i / 2.0f);
        sice_update<<<dim3(DD, NB), 256>>>(LLT, G, Cn, dec);
    }

    // Stage 5: final trace normalization + triuvec
    tracek<<<NB, 256>>>(LLT, tr);
    gather_out<<<dim3(DD, NB), 256>>>(LLT, tr, out);
}

// round 2
// speedup vs baseline: 1.4549x; 1.4549x over previous
#include <cuda_runtime.h>

#define NB   32
#define DD   256
#define MMs  784
#define CINc 2048
#define MAT  (DD*DD)          // 65536
#define BMAT (NB*MAT)         // 2,097,152
#define KC   16               // K chunk

// Scratch (device globals; no allocation anywhere)
__device__ float g_y[NB*DD*MMs];      // BN'd ReLU'd activations [b][d][m]
__device__ float g_mats[9u*BMAT];     // 9 batched 256x256 buffers
__device__ float g_small[16384];      // bn stats, rowmean, tr

// ---------------------------------------------------------------------------
__device__ __forceinline__ float warpReduce(float v) {
    #pragma unroll
    for (int o = 16; o; o >>= 1) v += __shfl_down_sync(0xffffffffu, v, o);
    return v;
}

// map upper-triangular tile index t in [0,10) -> (ti,tj), ti<=tj, 4x4 tiles
__device__ __forceinline__ void tilemap(int t, int& ti, int& tj) {
    if (t < 4)      { ti = 0; tj = t; }
    else if (t < 7) { ti = 1; tj = t - 3; }
    else if (t < 9) { ti = 2; tj = t - 5; }
    else            { ti = 3; tj = 3; }
}

// ===========================================================================
// GEMM core pieces (64x64 tile, 128 threads, 8x4 per thread, double-buffered)
// A stored transposed in smem As[k][m] (pitch 68); B straight Bs[k][n] or
// transposed depending on kernel.
// ===========================================================================

// compute one K-chunk from shared buffers
#define GEMM_COMPUTE(AsB, BsB)                                                 \
    {                                                                          \
        _Pragma("unroll")                                                      \
        for (int kk = 0; kk < KC; kk++) {                                      \
            float4 a0 = *(const float4*)&AsB[kk][tr8 * 8];                     \
            float4 a1 = *(const float4*)&AsB[kk][tr8 * 8 + 4];                 \
            float4 bq = *(const float4*)&BsB[kk][tc * 4];                      \
            float ar[8] = {a0.x,a0.y,a0.z,a0.w,a1.x,a1.y,a1.z,a1.w};           \
            float br[4] = {bq.x,bq.y,bq.z,bq.w};                               \
            _Pragma("unroll")                                                  \
            for (int i = 0; i < 8; i++)                                        \
                _Pragma("unroll")                                              \
                for (int j = 0; j < 4; j++)                                    \
                    acc[i][j] = fmaf(ar[i], br[j], acc[i][j]);                 \
        }                                                                      \
    }

// ---------------------------------------------------------------------------
// conv 1x1 GEMM: y[b][d][m] = sum_c w[d][c] * x[b][c][m]
// A = w [256 x 2048] (transposed into smem), B = x[b] [2048 x 784] straight.
// grid (13, 4, NB), 128 threads
// ---------------------------------------------------------------------------
__global__ __launch_bounds__(128, 6) void conv_gemm(
    const float* __restrict__ x, const float* __restrict__ w, float* __restrict__ y)
{
    const int b  = blockIdx.z;
    const int m0 = blockIdx.y * 64;
    const int n0 = blockIdx.x * 64;
    const float* Ap = w;
    const float* Bp = x + (size_t)b * CINc * MMs;
    float* Dp = y + (size_t)b * DD * MMs;

    __shared__ float As[2][KC][68];
    __shared__ float Bs[2][KC][68];
    const int tid = threadIdx.x;
    const int tc = tid & 15, tr8 = tid >> 4;

    float4 pa[2], pb[2];
    float acc[8][4] = {};

    // prologue: load chunk 0
    #pragma unroll
    for (int h = 0; h < 2; h++) {
        int fi = tid + 128 * h;
        int row = fi >> 2, q = fi & 3;
        pa[h] = *(const float4*)(Ap + (size_t)(m0 + row) * CINc + q * 4);
        int kr = fi >> 4, nc = fi & 15;
        int col = n0 + nc * 4;
        pb[h] = (col < MMs) ? *(const float4*)(Bp + (size_t)kr * MMs + col)
                            : make_float4(0.f,0.f,0.f,0.f);
    }
    #pragma unroll
    for (int h = 0; h < 2; h++) {
        int fi = tid + 128 * h;
        int row = fi >> 2, q = fi & 3;
        As[0][q*4+0][row] = pa[h].x; As[0][q*4+1][row] = pa[h].y;
        As[0][q*4+2][row] = pa[h].z; As[0][q*4+3][row] = pa[h].w;
        int kr = fi >> 4, nc = fi & 15;
        *(float4*)&Bs[0][kr][nc*4] = pb[h];
    }
    __syncthreads();

    const int NCH = CINc / KC;
    for (int ch = 0; ch < NCH; ch++) {
        const int buf = ch & 1;
        if (ch + 1 < NCH) {
            const int k0 = (ch + 1) * KC;
            #pragma unroll
            for (int h = 0; h < 2; h++) {
                int fi = tid + 128 * h;
                int row = fi >> 2, q = fi & 3;
                pa[h] = *(const float4*)(Ap + (size_t)(m0 + row) * CINc + k0 + q * 4);
                int kr = fi >> 4, nc = fi & 15;
                int col = n0 + nc * 4;
                pb[h] = (col < MMs) ? *(const float4*)(Bp + (size_t)(k0 + kr) * MMs + col)
                                    : make_float4(0.f,0.f,0.f,0.f);
            }
        }
        GEMM_COMPUTE(As[buf], Bs[buf]);
        if (ch + 1 < NCH) {
            const int nb = buf ^ 1;
            #pragma unroll
            for (int h = 0; h < 2; h++) {
                int fi = tid + 128 * h;
                int row = fi >> 2, q = fi & 3;
                As[nb][q*4+0][row] = pa[h].x; As[nb][q*4+1][row] = pa[h].y;
                As[nb][q*4+2][row] = pa[h].z; As[nb][q*4+3][row] = pa[h].w;
                int kr = fi >> 4, nc = fi & 15;
                *(float4*)&Bs[nb][kr][nc*4] = pb[h];
            }
            __syncthreads();
        }
    }

    #pragma unroll
    for (int i = 0; i < 8; i++) {
        const int r = m0 + tr8 * 8 + i;
        const int c = n0 + tc * 4;
        if (c < MMs)
            *(float4*)(Dp + (size_t)r * MMs + c) =
                make_float4(acc[i][0], acc[i][1], acc[i][2], acc[i][3]);
    }
}

// ---------------------------------------------------------------------------
// BN stats over (b, m) per channel d
// ---------------------------------------------------------------------------
__global__ void bn_stats(const float* __restrict__ y, float* __restrict__ mean,
                         float* __restrict__ rstd)
{
    const int d = blockIdx.x;
    const int t = threadIdx.x;
    float s = 0.f, s2 = 0.f;
    for (int b = 0; b < NB; b++) {
        const float* p = y + (size_t)b * DD * MMs + (size_t)d * MMs;
        for (int m = t; m < MMs; m += 256) { float v = p[m]; s += v; s2 = fmaf(v, v, s2); }
    }
    __shared__ float sh1[8], sh2[8];
    const int lane = t & 31, wid = t >> 5;
    s = warpReduce(s); s2 = warpReduce(s2);
    if (lane == 0) { sh1[wid] = s; sh2[wid] = s2; }
    __syncthreads();
    if (wid == 0) {
        s  = (lane < 8) ? sh1[lane] : 0.f;
        s2 = (lane < 8) ? sh2[lane] : 0.f;
        s = warpReduce(s); s2 = warpReduce(s2);
        if (lane == 0) {
            const float N = (float)(NB * MMs);
            float mu  = s / N;
            float var = s2 / N - mu * mu;
            mean[d] = mu;
            rstd[d] = rsqrtf(var + 1e-5f);
        }
    }
}

// ---------------------------------------------------------------------------
// BN apply + ReLU (in place) + per-(b,d) row mean
// ---------------------------------------------------------------------------
__global__ void bn_apply(float* __restrict__ y, const float* __restrict__ mean,
                         const float* __restrict__ rstd, const float* __restrict__ gamma,
                         const float* __restrict__ beta, float* __restrict__ rowmean)
{
    const int bd = blockIdx.x;
    const int d  = bd & (DD - 1);
    float* p = y + (size_t)bd * MMs;
    const float mu = mean[d], rs = rstd[d], g = gamma[d], be = beta[d];
    const int t = threadIdx.x;
    float s = 0.f;
    for (int m = t; m < MMs; m += 256) {
        float v = fmaf((p[m] - mu) * rs, g, be);
        v = fmaxf(v, 0.f);
        p[m] = v;
        s += v;
    }
    __shared__ float sh[8];
    const int lane = t & 31, wid = t >> 5;
    s = warpReduce(s);
    if (lane == 0) sh[wid] = s;
    __syncthreads();
    if (wid == 0) {
        s = (lane < 8) ? sh[lane] : 0.f;
        s = warpReduce(s);
        if (lane == 0) rowmean[bd] = s * (1.0f / MMs);
    }
}

// ---------------------------------------------------------------------------
// Covariance (symmetric, upper tiles only, exact mirror):
// C[b] = (Y Y^T)/784 - mu mu^T.  Both operands transposed into smem.
// grid (10, 1, NB), 128 threads
// ---------------------------------------------------------------------------
__global__ __launch_bounds__(128, 6) void cov_sym(
    const float* __restrict__ y, const float* __restrict__ rowmean, float* __restrict__ C)
{
    const int b = blockIdx.z;
    int ti, tj; tilemap(blockIdx.x, ti, tj);
    const int i0 = ti * 64, j0 = tj * 64;
    const float* Yb = y + (size_t)b * DD * MMs;

    __shared__ float As[2][KC][68];
    __shared__ float Bs[2][KC][68];
    const int tid = threadIdx.x;
    const int tc = tid & 15, tr8 = tid >> 4;

    float4 pa[2], pb[2];
    float acc[8][4] = {};

    #pragma unroll
    for (int h = 0; h < 2; h++) {
        int fi = tid + 128 * h;
        int row = fi >> 2, q = fi & 3;
        pa[h] = *(const float4*)(Yb + (size_t)(i0 + row) * MMs + q * 4);
        pb[h] = *(const float4*)(Yb + (size_t)(j0 + row) * MMs + q * 4);
    }
    #pragma unroll
    for (int h = 0; h < 2; h++) {
        int fi = tid + 128 * h;
        int row = fi >> 2, q = fi & 3;
        As[0][q*4+0][row] = pa[h].x; As[0][q*4+1][row] = pa[h].y;
        As[0][q*4+2][row] = pa[h].z; As[0][q*4+3][row] = pa[h].w;
        Bs[0][q*4+0][row] = pb[h].x; Bs[0][q*4+1][row] = pb[h].y;
        Bs[0][q*4+2][row] = pb[h].z; Bs[0][q*4+3][row] = pb[h].w;
    }
    __syncthreads();

    const int NCH = MMs / KC;   // 49
    for (int ch = 0; ch < NCH; ch++) {
        const int buf = ch & 1;
        if (ch + 1 < NCH) {
            const int k0 = (ch + 1) * KC;
            #pragma unroll
            for (int h = 0; h < 2; h++) {
                int fi = tid + 128 * h;
                int row = fi >> 2, q = fi & 3;
                pa[h] = *(const float4*)(Yb + (size_t)(i0 + row) * MMs + k0 + q * 4);
                pb[h] = *(const float4*)(Yb + (size_t)(j0 + row) * MMs + k0 + q * 4);
            }
        }
        GEMM_COMPUTE(As[buf], Bs[buf]);
        if (ch + 1 < NCH) {
            const int nb = buf ^ 1;
            #pragma unroll
            for (int h = 0; h < 2; h++) {
                int fi = tid + 128 * h;
                int row = fi >> 2, q = fi & 3;
                As[nb][q*4+0][row] = pa[h].x; As[nb][q*4+1][row] = pa[h].y;
                As[nb][q*4+2][row] = pa[h].z; As[nb][q*4+3][row] = pa[h].w;
                Bs[nb][q*4+0][row] = pb[h].x; Bs[nb][q*4+1][row] = pb[h].y;
                Bs[nb][q*4+2][row] = pb[h].z; Bs[nb][q*4+3][row] = pb[h].w;
            }
            __syncthreads();
        }
    }

    const float invM = 1.0f / (float)MMs;
    const float* mu = rowmean + b * DD;
    float* Cb = C + (size_t)b * MAT;
    #pragma unroll
    for (int i = 0; i < 8; i++) {
        const int r = i0 + tr8 * 8 + i;
        const float mi = mu[r];
        float4 o;
        const int c0 = j0 + tc * 4;
        o.x = acc[i][0] * invM - mi * mu[c0+0];
        o.y = acc[i][1] * invM - mi * mu[c0+1];
        o.z = acc[i][2] * invM - mi * mu[c0+2];
        o.w = acc[i][3] * invM - mi * mu[c0+3];
        *(float4*)(Cb + (size_t)r * DD + c0) = o;
        if (ti != tj) {   // exact mirror (same products, same order)
            Cb[(size_t)(c0+0) * DD + r] = o.x;
            Cb[(size_t)(c0+1) * DD + r] = o.y;
            Cb[(size_t)(c0+2) * DD + r] = o.z;
            Cb[(size_t)(c0+3) * DD + r] = o.w;
        }
    }
}

// ---------------------------------------------------------------------------
// Batched symmetric-output 256^3 GEMM, upper tiles, mirrored write.
// epi 0: D = P               (mirror)
// epi 1: D = 1.5I - 0.5P     (mirror)
// epi 2: D = P * rsqrt(tr)   (mirror)
// epi 3: fused SICE update: L = sice(L, Cn - P, dec)  (mirror; D is L in/out)
// grid (10, 1, NB), 128 threads
// ---------------------------------------------------------------------------
__device__ __forceinline__ float sice_f(float L, float g12, float dec)
{
    float lp = fmaxf(L, 0.f);
    float lm = fmaxf(-L, 0.f);
    lp = fmaxf(lp - dec * (g12 + 0.07f), 0.f);
    lm = fmaxf(lm - dec * (-g12 + 0.07f), 0.f);
    return lp - lm;
}

__global__ __launch_bounds__(128, 6) void bgemm_sym(
    const float* __restrict__ Ab, const float* __restrict__ Bb, float* __restrict__ Db,
    const float* __restrict__ tr, int epi, const float* __restrict__ Cn, float dec)
{
    const int b = blockIdx.z;
    int ti, tj; tilemap(blockIdx.x, ti, tj);
    const int m0 = ti * 64, n0 = tj * 64;
    const float* Ap = Ab + (size_t)b * MAT;
    const float* Bp = Bb + (size_t)b * MAT;
    float* Dp = Db + (size_t)b * MAT;

    __shared__ float As[2][KC][68];
    __shared__ float Bs[2][KC][68];
    const int tid = threadIdx.x;
    const int tc = tid & 15, tr8 = tid >> 4;

    float4 pa[2], pb[2];
    float acc[8][4] = {};

    #pragma unroll
    for (int h = 0; h < 2; h++) {
        int fi = tid + 128 * h;
        int row = fi >> 2, q = fi & 3;
        pa[h] = *(const float4*)(Ap + (size_t)(m0 + row) * DD + q * 4);
        int kr = fi >> 4, nc = fi & 15;
        pb[h] = *(const float4*)(Bp + (size_t)kr * DD + n0 + nc * 4);
    }
    #pragma unroll
    for (int h = 0; h < 2; h++) {
        int fi = tid + 128 * h;
        int row = fi >> 2, q = fi & 3;
        As[0][q*4+0][row] = pa[h].x; As[0][q*4+1][row] = pa[h].y;
        As[0][q*4+2][row] = pa[h].z; As[0][q*4+3][row] = pa[h].w;
        int kr = fi >> 4, nc = fi & 15;
        *(float4*)&Bs[0][kr][nc*4] = pb[h];
    }
    __syncthreads();

    const int NCH = DD / KC;   // 16
    for (int ch = 0; ch < NCH; ch++) {
        const int buf = ch & 1;
        if (ch + 1 < NCH) {
            const int k0 = (ch + 1) * KC;
            #pragma unroll
            for (int h = 0; h < 2; h++) {
                int fi = tid + 128 * h;
                int row = fi >> 2, q = fi & 3;
                pa[h] = *(const float4*)(Ap + (size_t)(m0 + row) * DD + k0 + q * 4);
                int kr = fi >> 4, nc = fi & 15;
                pb[h] = *(const float4*)(Bp + (size_t)(k0 + kr) * DD + n0 + nc * 4);
            }
        }
        GEMM_COMPUTE(As[buf], Bs[buf]);
        if (ch + 1 < NCH) {
            const int nb = buf ^ 1;
            #pragma unroll
            for (int h = 0; h < 2; h++) {
                int fi = tid + 128 * h;
                int row = fi >> 2, q = fi & 3;
                As[nb][q*4+0][row] = pa[h].x; As[nb][q*4+1][row] = pa[h].y;
                As[nb][q*4+2][row] = pa[h].z; As[nb][q*4+3][row] = pa[h].w;
                int kr = fi >> 4, nc = fi & 15;
                *(float4*)&Bs[nb][kr][nc*4] = pb[h];
            }
            __syncthreads();
        }
    }

    const float rs = (epi == 2) ? rsqrtf(tr[b]) : 1.0f;
    const float* Cb = (epi == 3) ? (Cn + (size_t)b * MAT) : nullptr;
    #pragma unroll
    for (int i = 0; i < 8; i++) {
        const int r = m0 + tr8 * 8 + i;
        const int c0 = n0 + tc * 4;
        float v[4];
        #pragma unroll
        for (int j = 0; j < 4; j++) v[j] = acc[i][j];
        if (epi == 1) {
            #pragma unroll
            for (int j = 0; j < 4; j++)
                v[j] = ((r == c0 + j) ? 1.5f : 0.0f) - 0.5f * v[j];
        } else if (epi == 2) {
            #pragma unroll
            for (int j = 0; j < 4; j++) v[j] *= rs;
        } else if (epi == 3) {
            #pragma unroll
            for (int j = 0; j < 4; j++) {
                float Lv = Dp[(size_t)r * DD + c0 + j];
                float g  = Cb[(size_t)r * DD + c0 + j] - v[j];
                v[j] = sice_f(Lv, g, dec);
            }
        }
        *(float4*)(Dp + (size_t)r * DD + c0) = make_float4(v[0], v[1], v[2], v[3]);
        if (ti != tj) {
            Dp[(size_t)(c0+0) * DD + r] = v[0];
            Dp[(size_t)(c0+1) * DD + r] = v[1];
            Dp[(size_t)(c0+2) * DD + r] = v[2];
            Dp[(size_t)(c0+3) * DD + r] = v[3];
        }
    }
}

// ---------------------------------------------------------------------------
// Fused pair: z<NB -> D1 = A1@B1 ; z>=NB -> D2 = A2@B2 (both symmetric, epi 0)
// grid (10, 1, 2*NB), 128 threads
// ---------------------------------------------------------------------------
__global__ __launch_bounds__(128, 6) void bgemm_pair(
    const float* __restrict__ A1, const float* __restrict__ B1, float* __restrict__ D1,
    const float* __restrict__ A2, const float* __restrict__ B2, float* __restrict__ D2)
{
    const int z = blockIdx.z;
    const int b = z & (NB - 1);
    const bool second = z >= NB;
    const float* Ap = (second ? A2 : A1) + (size_t)b * MAT;
    const float* Bp = (second ? B2 : B1) + (size_t)b * MAT;
    float* Dp = (second ? D2 : D1) + (size_t)b * MAT;

    int ti, tj; tilemap(blockIdx.x, ti, tj);
    const int m0 = ti * 64, n0 = tj * 64;

    __shared__ float As[2][KC][68];
    __shared__ float Bs[2][KC][68];
    const int tid = threadIdx.x;
    const int tc = tid & 15, tr8 = tid >> 4;

    float4 pa[2], pb[2];
    float acc[8][4] = {};

    #pragma unroll
    for (int h = 0; h < 2; h++) {
        int fi = tid + 128 * h;
        int row = fi >> 2, q = fi & 3;
        pa[h] = *(const float4*)(Ap + (size_t)(m0 + row) * DD + q * 4);
        int kr = fi >> 4, nc = fi & 15;
        pb[h] = *(const float4*)(Bp + (size_t)kr * DD + n0 + nc * 4);
    }
    #pragma unroll
    for (int h = 0; h < 2; h++) {
        int fi = tid + 128 * h;
        int row = fi >> 2, q = fi & 3;
        As[0][q*4+0][row] = pa[h].x; As[0][q*4+1][row] = pa[h].y;
        As[0][q*4+2][row] = pa[h].z; As[0][q*4+3][row] = pa[h].w;
        int kr = fi >> 4, nc = fi & 15;
        *(float4*)&Bs[0][kr][nc*4] = pb[h];
    }
    __syncthreads();

    const int NCH = DD / KC;
    for (int ch = 0; ch < NCH; ch++) {
        const int buf = ch & 1;
        if (ch + 1 < NCH) {
            const int k0 = (ch + 1) * KC;
            #pragma unroll
            for (int h = 0; h < 2; h++) {
                int fi = tid + 128 * h;
                int row = fi >> 2, q = fi & 3;
                pa[h] = *(const float4*)(Ap + (size_t)(m0 + row) * DD + k0 + q * 4);
                int kr = fi >> 4, nc = fi & 15;
                pb[h] = *(const float4*)(Bp + (size_t)(k0 + kr) * DD + n0 + nc * 4);
            }
        }
        GEMM_COMPUTE(As[buf], Bs[buf]);
        if (ch + 1 < NCH) {
            const int nb = buf ^ 1;
            #pragma unroll
            for (int h = 0; h < 2; h++) {
                int fi = tid + 128 * h;
                int row = fi >> 2, q = fi & 3;
                As[nb][q*4+0][row] = pa[h].x; As[nb][q*4+1][row] = pa[h].y;
                As[nb][q*4+2][row] = pa[h].z; As[nb][q*4+3][row] = pa[h].w;
                int kr = fi >> 4, nc = fi & 15;
                *(float4*)&Bs[nb][kr][nc*4] = pb[h];
            }
            __syncthreads();
        }
    }

    #pragma unroll
    for (int i = 0; i < 8; i++) {
        const int r = m0 + tr8 * 8 + i;
        const int c0 = n0 + tc * 4;
        *(float4*)(Dp + (size_t)r * DD + c0) =
            make_float4(acc[i][0], acc[i][1], acc[i][2], acc[i][3]);
        if (ti != tj) {
            Dp[(size_t)(c0+0) * DD + r] = acc[i][0];
            Dp[(size_t)(c0+1) * DD + r] = acc[i][1];
            Dp[(size_t)(c0+2) * DD + r] = acc[i][2];
            Dp[(size_t)(c0+3) * DD + r] = acc[i][3];
        }
    }
}

// ---------------------------------------------------------------------------
// small kernels
// ---------------------------------------------------------------------------
__global__ void tracek(const float* __restrict__ X, float* __restrict__ tr)
{
    const int b = blockIdx.x;
    const int t = threadIdx.x;
    float v = X[(size_t)b * MAT + t * 257];
    __shared__ float sh[8];
    const int lane = t & 31, wid = t >> 5;
    v = warpReduce(v);
    if (lane == 0) sh[wid] = v;
    __syncthreads();
    if (wid == 0) {
        v = (lane < 8) ? sh[lane] : 0.f;
        v = warpReduce(v);
        if (lane == 0) tr[b] = v;
    }
}

// trace of (X + diag(jitter-term))
__global__ void tracek_j(const float* __restrict__ X, const float* __restrict__ jitter,
                         float* __restrict__ tr)
{
    const int b = blockIdx.x;
    const int t = threadIdx.x;
    float v = X[(size_t)b * MAT + t * 257] + 1e-10f + 1e-9f * jitter[t];
    __shared__ float sh[8];
    const int lane = t & 31, wid = t >> 5;
    v = warpReduce(v);
    if (lane == 0) sh[wid] = v;
    __syncthreads();
    if (wid == 0) {
        v = (lane < 8) ? sh[lane] : 0.f;
        v = warpReduce(v);
        if (lane == 0) tr[b] = v;
    }
}

// in-place scale C /= tr[b]
__global__ void scalek(float* __restrict__ C, const float* __restrict__ tr)
{
    const int idx = blockIdx.x * 256 + threadIdx.x;
    C[idx] *= (1.0f / tr[idx >> 16]);
}

// A = (S + Ij)/tr[b];  ZY0 = 0.5*(3I - A)
__global__ void prep_ns(const float* __restrict__ S, const float* __restrict__ jitter,
                        const float* __restrict__ tr, float* __restrict__ A,
                        float* __restrict__ ZY)
{
    const int idx = blockIdx.x * 256 + threadIdx.x;
    const int b = idx >> 16, rc = idx & 65535, r = rc >> 8, c = rc & 255;
    float v = S[idx];
    if (r == c) v += 1e-10f + 1e-9f * jitter[r];
    float a = v * (1.0f / tr[b]);
    A[idx] = a;
    ZY[idx] = (r == c ? 1.5f : 0.0f) - 0.5f * a;
}

__global__ void gather_out(const float* __restrict__ L, const float* __restrict__ tr,
                           float* __restrict__ out)
{
    const int b = blockIdx.y, i = blockIdx.x, j = threadIdx.x;
    if (j < i) return;
    const float s = rsqrtf(tr[b]);
    const int k = i * 256 - (i * (i - 1)) / 2 + (j - i);
    out[(size_t)b * 32896 + k] = L[(size_t)b * MAT + i * 256 + j] * s;
}

// ---------------------------------------------------------------------------
// Host orchestration
// ---------------------------------------------------------------------------
static void run_inv(const float* S, const float* jitter, float* zz, float* tr,
                    float* A, float* Y, float* Z, float* Y2, float* Z2, float* ZYt)
{
    const dim3 gs(10, 1, NB);
    tracek_j<<<NB, 256>>>(S, jitter, tr);
    prep_ns<<<BMAT / 256, 256>>>(S, jitter, tr, A, Z);    // Z = ZY0
    bgemm_sym<<<gs, 128>>>(A, Z, Y, tr, 0, nullptr, 0.f); // Y = A @ ZY0
    float *Yc = Y, *Zc = Z, *Ya = Y2, *Za = Z2;
    for (int it = 0; it < 5; it++) {
        bgemm_sym<<<gs, 128>>>(Zc, Yc, ZYt, tr, 1, nullptr, 0.f);   // ZY = 1.5I-0.5 Z@Y
        bgemm_pair<<<dim3(10, 1, 2 * NB), 128>>>(Yc, ZYt, Ya, ZYt, Zc, Za);
        float* t1 = Yc; Yc = Ya; Ya = t1;
        float* t2 = Zc; Zc = Za; Za = t2;
    }
    bgemm_sym<<<gs, 128>>>(Zc, Yc, ZYt, tr, 1, nullptr, 0.f);
    bgemm_sym<<<gs, 128>>>(ZYt, Zc, zz, tr, 2, nullptr, 0.f);       // * tr^-0.5
}

extern "C" void kernel_launch(void* const* d_in, const int* in_sizes, int n_in,
                              void* d_out, int out_size)
{
    (void)in_sizes; (void)n_in; (void)out_size;
    const float* x      = (const float*)d_in[0];
    const float* w      = (const float*)d_in[1];
    const float* gamma  = (const float*)d_in[2];
    const float* beta   = (const float*)d_in[3];
    const float* jitter = (const float*)d_in[4];
    float* out = (float*)d_out;

    float *y, *mats, *small;
    cudaGetSymbolAddress((void**)&y, g_y);
    cudaGetSymbolAddress((void**)&mats, g_mats);
    cudaGetSymbolAddress((void**)&small, g_small);

    float* Cn  = mats + 0u * BMAT;
    float* A   = mats + 1u * BMAT;
    float* Y   = mats + 2u * BMAT;
    float* Z   = mats + 3u * BMAT;
    float* Y2  = mats + 4u * BMAT;
    float* Z2  = mats + 5u * BMAT;
    float* ZYt = mats + 6u * BMAT;
    float* zz  = mats + 7u * BMAT;
    float* LLT = mats + 8u * BMAT;

    float* bn_mean = small;
    float* bn_rstd = small + 256;
    float* rowmean = small + 512;
    float* tr      = small + 512 + NB * DD;

    const dim3 gs(10, 1, NB);

    // Stage 1: conv + BN + ReLU
    conv_gemm<<<dim3(13, 4, NB), 128>>>(x, w, y);
    bn_stats<<<DD, 256>>>(y, bn_mean, bn_rstd);
    bn_apply<<<NB * DD, 256>>>(y, bn_mean, bn_rstd, gamma, beta, rowmean);

    // Stage 2: covariance + trace normalize (Cn == normalized C == sym_C)
    cov_sym<<<gs, 128>>>(y, rowmean, Cn);
    tracek<<<NB, 256>>>(Cn, tr);
    scalek<<<BMAT / 256, 256>>>(Cn, tr);

    // Stage 3: LLT = inv_sqrtm(Cn + Ij)^2
    run_inv(Cn, jitter, zz, tr, A, Y, Z, Y2, Z2, ZYt);
    bgemm_sym<<<gs, 128>>>(zz, zz, LLT, tr, 0, nullptr, 0.f);

    // Stage 4: SICE loop (i=2 has dec==0 -> exact identity, skipped)
    for (int i = 0; i < 2; i++) {
        run_inv(LLT, jitter, zz, tr, A, Y, Z, Y2, Z2, ZYt);
        const float dec = 5.0f * (1.0f - (float)i / 2.0f);
        // fused: P = zz@zz ; L = sice(L, Cn - P, dec), symmetric mirror
        bgemm_sym<<<gs, 128>>>(zz, zz, LLT, tr, 3, Cn, dec);
    }

    // Stage 5: final trace normalization + triuvec
    tracek<<<NB, 256>>>(LLT, tr);
    gather_out<<<dim3(DD, NB), 256>>>(LLT, tr, out);
}